// round 6
// baseline (speedup 1.0000x reference)
#include <cuda_runtime.h>
#include <cuda_bf16.h>
#include <cstdint>

// Problem constants (fixed by the reference)
#define NNODES 100000
#define DEG    16
#define FDIM   128
#define HDIM   128
#define ODIM   128
#define BATCH  8192

// Scratch in __device__ globals (no cudaMalloc allowed)
__device__ float    g_agg1[(size_t)NNODES * FDIM];    // 51.2 MB
__device__ float    g_h1  [(size_t)NNODES * HDIM];    // 51.2 MB
__device__ float    g_agg2[(size_t)BATCH  * HDIM];    //  4.2 MB
__device__ uint32_t g_feat16[(size_t)NNODES * 64];    // 25.6 MB bf16x2-packed features
// Pre-split, transposed weights: [n][k-pair] packed bf16x2 (k even in low half)
__device__ uint32_t g_w1t_hi[128 * 128];
__device__ uint32_t g_w1t_lo[128 * 128];
__device__ uint32_t g_w2t_hi[128 * 128];
__device__ uint32_t g_w2t_lo[128 * 128];

// ---------------------------------------------------------------------------
// helpers
// ---------------------------------------------------------------------------
__device__ __forceinline__ uint32_t pack_bf16(float lo, float hi) {
    __nv_bfloat162 h = __floats2bfloat162_rn(lo, hi);   // .x = lo (low 16 bits)
    return *reinterpret_cast<uint32_t*>(&h);
}

__device__ __forceinline__ void split_bf16(float x, float& hf, float& lf) {
    __nv_bfloat16 h = __float2bfloat16_rn(x);
    hf = __bfloat162float(h);
    lf = x - hf;
}

__device__ __forceinline__ void mma_bf16(float c[4],
                                         const uint32_t a[4],
                                         uint32_t b0, uint32_t b1) {
    asm volatile(
        "mma.sync.aligned.m16n8k16.row.col.f32.bf16.bf16.f32 "
        "{%0,%1,%2,%3}, {%4,%5,%6,%7}, {%8,%9}, {%0,%1,%2,%3};"
        : "+f"(c[0]), "+f"(c[1]), "+f"(c[2]), "+f"(c[3])
        : "r"(a[0]), "r"(a[1]), "r"(a[2]), "r"(a[3]), "r"(b0), "r"(b1));
}

#define LDSM4(r, addr)                                                         \
    asm volatile("ldmatrix.sync.aligned.m8n8.x4.shared.b16 {%0,%1,%2,%3}, [%4];" \
                 : "=r"((r)[0]), "=r"((r)[1]), "=r"((r)[2]), "=r"((r)[3])      \
                 : "r"(addr))

__device__ __forceinline__ void cp_async16(uint32_t smem_addr, const void* gptr) {
    asm volatile("cp.async.ca.shared.global [%0], [%1], 16;\n"
                 :: "r"(smem_addr), "l"(gptr));
}
__device__ __forceinline__ void cp_async_commit() {
    asm volatile("cp.async.commit_group;\n" ::: "memory");
}
__device__ __forceinline__ void cp_async_wait0() {
    asm volatile("cp.async.wait_group 0;\n" ::: "memory");
}

// ---------------------------------------------------------------------------
// Weight prep: W[256][128] f32 -> Wt_hi/Wt_lo[n][k/2] packed bf16x2
// ---------------------------------------------------------------------------
__global__ __launch_bounds__(256) void prep_w_kernel(
    const float* __restrict__ W, uint32_t* __restrict__ Wt_hi, uint32_t* __restrict__ Wt_lo)
{
    int idx = blockIdx.x * blockDim.x + threadIdx.x;   // 0..16383
    if (idx >= 128 * 128) return;
    int n  = idx >> 7;          // 0..127
    int kp = idx & 127;         // k-pair 0..127
    float x0 = W[(2 * kp + 0) * 128 + n];
    float x1 = W[(2 * kp + 1) * 128 + n];
    float h0, l0, h1, l1;
    split_bf16(x0, h0, l0);
    split_bf16(x1, h1, l1);
    Wt_hi[n * 128 + kp] = pack_bf16(h0, h1);
    Wt_lo[n * 128 + kp] = pack_bf16(l0, l1);
}

// ---------------------------------------------------------------------------
// features f32 -> packed bf16x2 (one float4 -> one uint2 per thread)
// ---------------------------------------------------------------------------
__global__ __launch_bounds__(256) void feat2bf16_kernel(
    const float4* __restrict__ src, uint2* __restrict__ dst, int n4)
{
    int i = blockIdx.x * blockDim.x + threadIdx.x;
    if (i >= n4) return;
    float4 v = src[i];
    dst[i] = make_uint2(pack_bf16(v.x, v.y), pack_bf16(v.z, v.w));
}

// ---------------------------------------------------------------------------
// Layer-1 aggregation from bf16-packed features (halved gather traffic).
// One warp per node; lane covers elems 4l..4l+3 (uint2 = 4 bf16). f32 accum.
// ---------------------------------------------------------------------------
__global__ __launch_bounds__(256) void agg_bf16_kernel(
    const uint2* __restrict__ src,
    const int*   __restrict__ nbr,
    float4*      __restrict__ out,
    int nrows)
{
    int warp = (blockIdx.x * blockDim.x + threadIdx.x) >> 5;
    int lane = threadIdx.x & 31;
    if (warp >= nrows) return;

    const int* nb = nbr + (long long)warp * DEG;
    float a0 = 0.f, a1 = 0.f, a2 = 0.f, a3 = 0.f;
#pragma unroll
    for (int j = 0; j < DEG; j++) {
        int idx = nb[j];
        uint2 v = src[(long long)idx * 32 + lane];
        __nv_bfloat162 p0 = *reinterpret_cast<__nv_bfloat162*>(&v.x);
        __nv_bfloat162 p1 = *reinterpret_cast<__nv_bfloat162*>(&v.y);
        a0 += __bfloat162float(p0.x); a1 += __bfloat162float(p0.y);
        a2 += __bfloat162float(p1.x); a3 += __bfloat162float(p1.y);
    }
    const float s = 1.0f / (float)DEG;
    out[(long long)warp * 32 + lane] = make_float4(a0 * s, a1 * s, a2 * s, a3 * s);
}

// ---------------------------------------------------------------------------
// Layer-2 aggregation (f32 rows of 128). One warp per batch row.
// ---------------------------------------------------------------------------
__global__ __launch_bounds__(256) void agg_kernel(
    const float4* __restrict__ src,
    const int*    __restrict__ nbr,
    const int*    __restrict__ nodes,
    float4*       __restrict__ out,
    int nrows)
{
    int warp = (blockIdx.x * blockDim.x + threadIdx.x) >> 5;
    int lane = threadIdx.x & 31;
    if (warp >= nrows) return;

    int node = nodes ? nodes[warp] : warp;
    const int* nb = nbr + (long long)node * DEG;

    float4 acc = make_float4(0.f, 0.f, 0.f, 0.f);
#pragma unroll
    for (int j = 0; j < DEG; j++) {
        int idx = nb[j];
        float4 v = src[(long long)idx * 32 + lane];
        acc.x += v.x; acc.y += v.y; acc.z += v.z; acc.w += v.w;
    }
    const float s = 1.0f / (float)DEG;
    acc.x *= s; acc.y *= s; acc.z *= s; acc.w *= s;
    out[(long long)warp * 32 + lane] = acc;
}

// ---------------------------------------------------------------------------
// Tensor-core GEMM, software-pipelined, double-buffered, ldmatrix fragments.
// C[M,128] = [A0 | A1] @ W, K=256, bf16 2-term split (3 mma per k16 step).
// Block 128x128, BK=32 (8 k-tiles), 8 warps (4 M x 2 N), warp tile 32x64.
// ---------------------------------------------------------------------------
#define BM  128
#define BK  32
#define KT  8            // K tiles (256 / 32)
#define SMS 20           // smem row stride (uint32), conflict-free for ldmatrix
#define BUFW (128 * SMS) // words per array per buffer

__global__ __launch_bounds__(256) void gemm_tc_kernel(
    const float*    __restrict__ A0,
    const float*    __restrict__ A1,
    const int*      __restrict__ rowmap,
    const uint32_t* __restrict__ Wt_hi,
    const uint32_t* __restrict__ Wt_lo,
    float*          __restrict__ C,
    int M)
{
    extern __shared__ uint32_t smem[];
    uint32_t* as_hi = smem;               // [2][128][SMS]
    uint32_t* as_lo = smem + 2 * BUFW;
    uint32_t* bs_hi = smem + 4 * BUFW;
    uint32_t* bs_lo = smem + 6 * BUFW;
#define ASH(b,r,c) as_hi[(b) * BUFW + (r) * SMS + (c)]
#define ASL(b,r,c) as_lo[(b) * BUFW + (r) * SMS + (c)]
#define BSH(b,r,c) bs_hi[(b) * BUFW + (r) * SMS + (c)]
#define BSL(b,r,c) bs_lo[(b) * BUFW + (r) * SMS + (c)]

    const int tid  = threadIdx.x;
    const int lane = tid & 31;
    const int warp = tid >> 5;
    const int wm   = warp & 3;    // 4 m-tiles of 32 rows
    const int wn   = warp >> 2;   // 2 n-tiles of 64 cols
    const int g    = lane >> 2;
    const int tig  = lane & 3;
    const int block_row = blockIdx.x * BM;

    float acc[2][8][4];
#pragma unroll
    for (int mi = 0; mi < 2; mi++)
#pragma unroll
        for (int ni = 0; ni < 8; ni++)
#pragma unroll
            for (int j = 0; j < 4; j++) acc[mi][ni][j] = 0.f;

    const int arow  = tid >> 1;          // 0..127 (A smem row this thread fills)
    const int aq0   = (tid & 1) * 4;     // first float4 quad of this thread
    const int brow  = tid >> 1;          // 0..127 (B smem row)
    const int bpart = tid & 1;

    // resolve gathered A0 row pointer once
    int grow = block_row + arow;
    const float* a0row = nullptr;
    const float* a1row = nullptr;
    if (grow < M) {
        int src_row = rowmap ? rowmap[grow] : grow;
        a0row = A0 + (long long)src_row * FDIM;
        a1row = A1 + (long long)grow * HDIM;
    }

    // smem byte addresses for this thread's B cp.async destinations (buffer 0)
    uint32_t bsh_base = (uint32_t)__cvta_generic_to_shared(&BSH(0, brow, 0));
    uint32_t bsl_base = (uint32_t)__cvta_generic_to_shared(&BSL(0, brow, 0));

    // ldmatrix lane addresses (buffer 0, kk=0)
    const int lrow = lane & 15;
    const int lkp  = (lane >> 4) * 4;
    uint32_t a_ad_hi[2], a_ad_lo[2], b_ad_hi[4], b_ad_lo[4];
#pragma unroll
    for (int mi = 0; mi < 2; mi++) {
        int r = wm * 32 + mi * 16 + lrow;
        a_ad_hi[mi] = (uint32_t)__cvta_generic_to_shared(&ASH(0, r, lkp));
        a_ad_lo[mi] = (uint32_t)__cvta_generic_to_shared(&ASL(0, r, lkp));
    }
#pragma unroll
    for (int nj = 0; nj < 4; nj++) {
        int c = wn * 64 + nj * 16 + lrow;
        b_ad_hi[nj] = (uint32_t)__cvta_generic_to_shared(&BSH(0, c, lkp));
        b_ad_lo[nj] = (uint32_t)__cvta_generic_to_shared(&BSL(0, c, lkp));
    }

#define STAGE_B(t, b) do {                                                     \
        int kp0 = (t) * (BK / 2);                                              \
        _Pragma("unroll")                                                      \
        for (int i = 0; i < 2; i++) {                                          \
            int q = bpart * 2 + i;                                             \
            cp_async16(bsh_base + (b) * BUFW * 4 + q * 16,                     \
                       Wt_hi + brow * 128 + kp0 + q * 4);                      \
            cp_async16(bsl_base + (b) * BUFW * 4 + q * 16,                     \
                       Wt_lo + brow * 128 + kp0 + q * 4);                      \
        }                                                                      \
    } while (0)

#define LOAD_A(t, va) do {                                                     \
        const float* p = ((t) < 4) ? a0row : a1row;                            \
        int akofs = ((t) & 3) * BK;                                            \
        _Pragma("unroll")                                                      \
        for (int i = 0; i < 4; i++) {                                          \
            int q = aq0 + i;                                                   \
            va[i] = p ? *reinterpret_cast<const float4*>(p + akofs + q * 4)    \
                      : make_float4(0.f, 0.f, 0.f, 0.f);                       \
        }                                                                      \
    } while (0)

#define STORE_A(b, va) do {                                                    \
        _Pragma("unroll")                                                      \
        for (int i = 0; i < 4; i++) {                                          \
            int q = aq0 + i;                                                   \
            float hx, lx, hy, ly, hz, lz, hw, lw;                              \
            split_bf16(va[i].x, hx, lx); split_bf16(va[i].y, hy, ly);          \
            split_bf16(va[i].z, hz, lz); split_bf16(va[i].w, hw, lw);          \
            ASH((b), arow, q * 2 + 0) = pack_bf16(hx, hy);                     \
            ASH((b), arow, q * 2 + 1) = pack_bf16(hz, hw);                     \
            ASL((b), arow, q * 2 + 0) = pack_bf16(lx, ly);                     \
            ASL((b), arow, q * 2 + 1) = pack_bf16(lz, lw);                     \
        }                                                                      \
    } while (0)

    // ---- prologue: tile 0 -> buffer 0
    {
        STAGE_B(0, 0);
        cp_async_commit();
        float4 va[4];
        LOAD_A(0, va);
        STORE_A(0, va);
        cp_async_wait0();
    }

    // ---- main loop
    for (int t = 0; t < KT; t++) {
        __syncthreads();
        const int cb = t & 1;
        const int nb = (t + 1) & 1;
        const bool have_next = (t + 1 < KT);

        float4 va[4];
        if (have_next) {
            STAGE_B(t + 1, nb);
            cp_async_commit();
            LOAD_A(t + 1, va);
        }

        // ---- compute on buffer cb: 2 k16 steps, ldmatrix fragments
#pragma unroll
        for (int kk = 0; kk < 2; kk++) {
            const uint32_t off = cb * (BUFW * 4) + kk * 32;   // bytes
            uint32_t ah[2][4], al[2][4];
            LDSM4(ah[0], a_ad_hi[0] + off);
            LDSM4(ah[1], a_ad_hi[1] + off);
            LDSM4(al[0], a_ad_lo[0] + off);
            LDSM4(al[1], a_ad_lo[1] + off);
#pragma unroll
            for (int nj = 0; nj < 4; nj++) {
                uint32_t bh[4], bl[4];
                LDSM4(bh, b_ad_hi[nj] + off);
                LDSM4(bl, b_ad_lo[nj] + off);
#pragma unroll
                for (int s = 0; s < 2; s++) {
                    const int ni = nj * 2 + s;
#pragma unroll
                    for (int mi = 0; mi < 2; mi++) {
                        mma_bf16(acc[mi][ni], ah[mi], bh[s], bh[s + 2]);
                        mma_bf16(acc[mi][ni], ah[mi], bl[s], bl[s + 2]);
                        mma_bf16(acc[mi][ni], al[mi], bh[s], bh[s + 2]);
                    }
                }
            }
        }

        if (have_next) {
            STORE_A(nb, va);
            cp_async_wait0();
        }
    }

    // ---- epilogue: float2 stores
#pragma unroll
    for (int mi = 0; mi < 2; mi++) {
        int r0 = block_row + wm * 32 + mi * 16 + g;
#pragma unroll
        for (int ni = 0; ni < 8; ni++) {
            int col = wn * 64 + ni * 8 + tig * 2;
            if (r0 < M)
                *reinterpret_cast<float2*>(C + (long long)r0 * ODIM + col) =
                    make_float2(acc[mi][ni][0], acc[mi][ni][1]);
            if (r0 + 8 < M)
                *reinterpret_cast<float2*>(C + (long long)(r0 + 8) * ODIM + col) =
                    make_float2(acc[mi][ni][2], acc[mi][ni][3]);
        }
    }
}

// ---------------------------------------------------------------------------
// kernel_launch
// inputs: 0=features[N,128] f32, 1=w1[256,128] f32, 2=w2[256,128] f32,
//         3=neighbor_idx[N,16] i32, 4=nodes[B] i32 ; out = [B,128] f32
// ---------------------------------------------------------------------------
extern "C" void kernel_launch(void* const* d_in, const int* in_sizes, int n_in,
                              void* d_out, int out_size)
{
    const float* features = (const float*)d_in[0];
    const float* w1       = (const float*)d_in[1];
    const float* w2       = (const float*)d_in[2];
    const int*   nbr      = (const int*)  d_in[3];
    const int*   nodes    = (const int*)  d_in[4];
    float*       out      = (float*)d_out;

    const int N  = in_sizes[0] / FDIM;   // 100000
    const int Bn = in_sizes[4];          // 8192

    float *agg1, *h1, *agg2;
    uint32_t *feat16, *w1t_hi, *w1t_lo, *w2t_hi, *w2t_lo;
    cudaGetSymbolAddress((void**)&agg1,   g_agg1);
    cudaGetSymbolAddress((void**)&h1,     g_h1);
    cudaGetSymbolAddress((void**)&agg2,   g_agg2);
    cudaGetSymbolAddress((void**)&feat16, g_feat16);
    cudaGetSymbolAddress((void**)&w1t_hi, g_w1t_hi);
    cudaGetSymbolAddress((void**)&w1t_lo, g_w1t_lo);
    cudaGetSymbolAddress((void**)&w2t_hi, g_w2t_hi);
    cudaGetSymbolAddress((void**)&w2t_lo, g_w2t_lo);

    const int smem_bytes = 8 * BUFW * 4;   // 81920 B
    static bool attr_set = false;
    if (!attr_set) {
        cudaFuncSetAttribute(gemm_tc_kernel,
                             cudaFuncAttributeMaxDynamicSharedMemorySize, smem_bytes);
        attr_set = true;
    }

    // 0) pre-split/transpose weights + bf16 feature copy
    prep_w_kernel<<<64, 256>>>(w1, w1t_hi, w1t_lo);
    prep_w_kernel<<<64, 256>>>(w2, w2t_hi, w2t_lo);
    {
        int n4 = N * 32;
        feat2bf16_kernel<<<(n4 + 255) / 256, 256>>>((const float4*)features,
                                                    (uint2*)feat16, n4);
    }

    // 1) agg1 = mean neighbor features (bf16 gather, f32 accumulate)
    agg_bf16_kernel<<<(N + 7) / 8, 256>>>((const uint2*)feat16, nbr,
                                          (float4*)agg1, N);
    // 2) h1 = [features | agg1] @ w1   (tensor cores, pipelined)
    gemm_tc_kernel<<<(N + BM - 1) / BM, 256, smem_bytes>>>(
        features, agg1, nullptr, w1t_hi, w1t_lo, h1, N);
    // 3) agg2 = mean neighbor h1 over the batch nodes (f32 gather)
    agg_kernel<<<(Bn + 7) / 8, 256>>>((const float4*)h1, nbr, nodes,
                                      (float4*)agg2, Bn);
    // 4) out = [h1[nodes] | agg2] @ w2   (tensor cores, pipelined)
    gemm_tc_kernel<<<(Bn + BM - 1) / BM, 256, smem_bytes>>>(
        h1, agg2, nodes, w2t_hi, w2t_lo, out, Bn);
}

// round 8
// speedup vs baseline: 1.0871x; 1.0871x over previous
#include <cuda_runtime.h>
#include <cuda_bf16.h>
#include <cstdint>

// Problem constants (fixed by the reference)
#define NNODES 100000
#define DEG    16
#define FDIM   128
#define HDIM   128
#define ODIM   128
#define BATCH  8192

// Scratch in __device__ globals (no cudaMalloc allowed)
__device__ float    g_agg1[(size_t)NNODES * FDIM];   // 51.2 MB
__device__ float    g_h1  [(size_t)NNODES * HDIM];   // 51.2 MB
__device__ float    g_agg2[(size_t)BATCH  * HDIM];   //  4.2 MB
// Pre-split, transposed weights: [n][k-pair] packed bf16x2 (k even in low half)
__device__ uint32_t g_w1t_hi[128 * 128];
__device__ uint32_t g_w1t_lo[128 * 128];
__device__ uint32_t g_w2t_hi[128 * 128];
__device__ uint32_t g_w2t_lo[128 * 128];

// ---------------------------------------------------------------------------
// helpers
// ---------------------------------------------------------------------------
__device__ __forceinline__ uint32_t pack_bf16(float lo, float hi) {
    __nv_bfloat162 h = __floats2bfloat162_rn(lo, hi);   // .x = lo (low 16 bits)
    return *reinterpret_cast<uint32_t*>(&h);
}

__device__ __forceinline__ void split_bf16(float x, float& hf, float& lf) {
    __nv_bfloat16 h = __float2bfloat16_rn(x);
    hf = __bfloat162float(h);
    lf = x - hf;
}

__device__ __forceinline__ void mma_bf16(float c[4],
                                         const uint32_t a[4],
                                         uint32_t b0, uint32_t b1) {
    asm volatile(
        "mma.sync.aligned.m16n8k16.row.col.f32.bf16.bf16.f32 "
        "{%0,%1,%2,%3}, {%4,%5,%6,%7}, {%8,%9}, {%0,%1,%2,%3};"
        : "+f"(c[0]), "+f"(c[1]), "+f"(c[2]), "+f"(c[3])
        : "r"(a[0]), "r"(a[1]), "r"(a[2]), "r"(a[3]), "r"(b0), "r"(b1));
}

#define LDSM4(r, addr)                                                         \
    asm volatile("ldmatrix.sync.aligned.m8n8.x4.shared.b16 {%0,%1,%2,%3}, [%4];" \
                 : "=r"((r)[0]), "=r"((r)[1]), "=r"((r)[2]), "=r"((r)[3])      \
                 : "r"(addr))

__device__ __forceinline__ void cp_async16(uint32_t smem_addr, const void* gptr) {
    asm volatile("cp.async.ca.shared.global [%0], [%1], 16;\n"
                 :: "r"(smem_addr), "l"(gptr));
}
__device__ __forceinline__ void cp_async_commit() {
    asm volatile("cp.async.commit_group;\n" ::: "memory");
}
__device__ __forceinline__ void cp_async_wait0() {
    asm volatile("cp.async.wait_group 0;\n" ::: "memory");
}

// ---------------------------------------------------------------------------
// Weight prep: W[256][128] f32 -> Wt_hi/Wt_lo[n][k/2] packed bf16x2
// ---------------------------------------------------------------------------
__global__ __launch_bounds__(256) void prep_w_kernel(
    const float* __restrict__ W, uint32_t* __restrict__ Wt_hi, uint32_t* __restrict__ Wt_lo)
{
    int idx = blockIdx.x * blockDim.x + threadIdx.x;   // 0..16383
    if (idx >= 128 * 128) return;
    int n  = idx >> 7;          // 0..127
    int kp = idx & 127;         // k-pair 0..127
    float x0 = W[(2 * kp + 0) * 128 + n];
    float x1 = W[(2 * kp + 1) * 128 + n];
    float h0, l0, h1, l1;
    split_bf16(x0, h0, l0);
    split_bf16(x1, h1, l1);
    Wt_hi[n * 128 + kp] = pack_bf16(h0, h1);
    Wt_lo[n * 128 + kp] = pack_bf16(l0, l1);
}

// ---------------------------------------------------------------------------
// Aggregation: out[i,:] = mean_j src[nbr[map(i)*DEG + j], :]   (rows of 128 f32)
// One warp per output row; each lane owns one float4. (L2/LTS-cap bound.)
// ---------------------------------------------------------------------------
__global__ __launch_bounds__(256) void agg_kernel(
    const float4* __restrict__ src,
    const int*    __restrict__ nbr,
    const int*    __restrict__ nodes,
    float4*       __restrict__ out,
    int nrows)
{
    int warp = (blockIdx.x * blockDim.x + threadIdx.x) >> 5;
    int lane = threadIdx.x & 31;
    if (warp >= nrows) return;

    int node = nodes ? nodes[warp] : warp;
    const int* nb = nbr + (long long)node * DEG;

    float4 acc = make_float4(0.f, 0.f, 0.f, 0.f);
#pragma unroll
    for (int j = 0; j < DEG; j++) {
        int idx = nb[j];
        float4 v = src[(long long)idx * 32 + lane];
        acc.x += v.x; acc.y += v.y; acc.z += v.z; acc.w += v.w;
    }
    const float s = 1.0f / (float)DEG;
    acc.x *= s; acc.y *= s; acc.z *= s; acc.w *= s;
    out[(long long)warp * 32 + lane] = acc;
}

// ---------------------------------------------------------------------------
// Tensor-core GEMM, software-pipelined, double-buffered, ldmatrix fragments.
// C[M,128] = [A0 | A1] @ W, K=256, bf16 2-term split (3 mma per k16 step).
// Block 128x128, BK=32 (8 k-tiles), 8 warps (4 M x 2 N), warp tile 32x64.
// Register-pressure managed: minBlocksPerSM=2; va dies after kk=0 compute.
// ---------------------------------------------------------------------------
#define BM  128
#define BK  32
#define KT  8            // K tiles (256 / 32)
#define SMS 20           // smem row stride (uint32), conflict-free for ldmatrix
#define BUFW (128 * SMS) // words per array per buffer

__global__ __launch_bounds__(256, 2) void gemm_tc_kernel(
    const float*    __restrict__ A0,
    const float*    __restrict__ A1,
    const int*      __restrict__ rowmap,
    const uint32_t* __restrict__ Wt_hi,
    const uint32_t* __restrict__ Wt_lo,
    float*          __restrict__ C,
    int M)
{
    extern __shared__ uint32_t smem[];
    uint32_t* as_hi = smem;               // [2][128][SMS]
    uint32_t* as_lo = smem + 2 * BUFW;
    uint32_t* bs_hi = smem + 4 * BUFW;
    uint32_t* bs_lo = smem + 6 * BUFW;
#define ASH(b,r,c) as_hi[(b) * BUFW + (r) * SMS + (c)]
#define ASL(b,r,c) as_lo[(b) * BUFW + (r) * SMS + (c)]
#define BSH(b,r,c) bs_hi[(b) * BUFW + (r) * SMS + (c)]
#define BSL(b,r,c) bs_lo[(b) * BUFW + (r) * SMS + (c)]

    const int tid  = threadIdx.x;
    const int lane = tid & 31;
    const int warp = tid >> 5;
    const int wm   = warp & 3;    // 4 m-tiles of 32 rows
    const int wn   = warp >> 2;   // 2 n-tiles of 64 cols
    const int g    = lane >> 2;
    const int tig  = lane & 3;
    const int block_row = blockIdx.x * BM;

    float acc[2][8][4];
#pragma unroll
    for (int mi = 0; mi < 2; mi++)
#pragma unroll
        for (int ni = 0; ni < 8; ni++)
#pragma unroll
            for (int j = 0; j < 4; j++) acc[mi][ni][j] = 0.f;

    const int arow  = tid >> 1;          // 0..127 (A smem row this thread fills)
    const int aq0   = (tid & 1) * 4;     // first float4 quad of this thread
    const int brow  = tid >> 1;          // 0..127 (B smem row)
    const int bpart = tid & 1;

    // resolve gathered A0 row pointer once
    int grow = block_row + arow;
    const float* a0row = nullptr;
    const float* a1row = nullptr;
    if (grow < M) {
        int src_row = rowmap ? rowmap[grow] : grow;
        a0row = A0 + (long long)src_row * FDIM;
        a1row = A1 + (long long)grow * HDIM;
    }

    // cp.async destinations for B (buffer 0 base)
    uint32_t bsh_base = (uint32_t)__cvta_generic_to_shared(&BSH(0, brow, 0));
    uint32_t bsl_base = (uint32_t)__cvta_generic_to_shared(&BSL(0, brow, 0));

    // ldmatrix base addresses (buffer 0, kk=0); offsets derived with constants.
    const int lrow = lane & 15;
    const int lkp  = (lane >> 4) * 4;
    const uint32_t a_base =
        (uint32_t)__cvta_generic_to_shared(&ASH(0, wm * 32 + lrow, lkp));
    const uint32_t b_base =
        (uint32_t)__cvta_generic_to_shared(&BSH(0, wn * 64 + lrow, lkp));
    const uint32_t LO_OFF  = 2 * BUFW * 4;     // as_lo - as_hi (bytes), same for B
    const uint32_t MI_OFF  = 16 * SMS * 4;     // +16 rows
    const uint32_t NJ_OFF  = 16 * SMS * 4;     // +16 cols

#define STAGE_B(t, b) do {                                                     \
        int kp0 = (t) * (BK / 2);                                              \
        _Pragma("unroll")                                                      \
        for (int i = 0; i < 2; i++) {                                          \
            int q = bpart * 2 + i;                                             \
            cp_async16(bsh_base + (b) * BUFW * 4 + q * 16,                     \
                       Wt_hi + brow * 128 + kp0 + q * 4);                      \
            cp_async16(bsl_base + (b) * BUFW * 4 + q * 16,                     \
                       Wt_lo + brow * 128 + kp0 + q * 4);                      \
        }                                                                      \
    } while (0)

#define LOAD_A(t, va) do {                                                     \
        const float* p = ((t) < 4) ? a0row : a1row;                            \
        int akofs = ((t) & 3) * BK;                                            \
        _Pragma("unroll")                                                      \
        for (int i = 0; i < 4; i++) {                                          \
            int q = aq0 + i;                                                   \
            va[i] = p ? *reinterpret_cast<const float4*>(p + akofs + q * 4)    \
                      : make_float4(0.f, 0.f, 0.f, 0.f);                       \
        }                                                                      \
    } while (0)

#define STORE_A(b, va) do {                                                    \
        _Pragma("unroll")                                                      \
        for (int i = 0; i < 4; i++) {                                          \
            int q = aq0 + i;                                                   \
            float hx, lx, hy, ly, hz, lz, hw, lw;                              \
            split_bf16(va[i].x, hx, lx); split_bf16(va[i].y, hy, ly);          \
            split_bf16(va[i].z, hz, lz); split_bf16(va[i].w, hw, lw);          \
            ASH((b), arow, q * 2 + 0) = pack_bf16(hx, hy);                     \
            ASH((b), arow, q * 2 + 1) = pack_bf16(hz, hw);                     \
            ASL((b), arow, q * 2 + 0) = pack_bf16(lx, ly);                     \
            ASL((b), arow, q * 2 + 1) = pack_bf16(lz, lw);                     \
        }                                                                      \
    } while (0)

    // one k16 compute step on buffer cb, sub-step kk (0/1)
#define COMPUTE_KK(cb, kk) do {                                                \
        const uint32_t off = (cb) * (BUFW * 4) + (kk) * 32;                    \
        uint32_t ah[2][4], al[2][4];                                           \
        LDSM4(ah[0], a_base + off);                                            \
        LDSM4(ah[1], a_base + off + MI_OFF);                                   \
        LDSM4(al[0], a_base + off + LO_OFF);                                   \
        LDSM4(al[1], a_base + off + LO_OFF + MI_OFF);                          \
        _Pragma("unroll")                                                      \
        for (int nj = 0; nj < 4; nj++) {                                       \
            uint32_t bh[4], bl[4];                                             \
            LDSM4(bh, b_base + off + nj * NJ_OFF);                             \
            LDSM4(bl, b_base + off + nj * NJ_OFF + LO_OFF);                    \
            _Pragma("unroll")                                                  \
            for (int s = 0; s < 2; s++) {                                      \
                const int ni = nj * 2 + s;                                     \
                _Pragma("unroll")                                              \
                for (int mi = 0; mi < 2; mi++) {                               \
                    mma_bf16(acc[mi][ni], ah[mi], bh[s], bh[s + 2]);           \
                    mma_bf16(acc[mi][ni], ah[mi], bl[s], bl[s + 2]);           \
                    mma_bf16(acc[mi][ni], al[mi], bh[s], bh[s + 2]);           \
                }                                                              \
            }                                                                  \
        }                                                                      \
    } while (0)

    // ---- prologue: tile 0 -> buffer 0
    {
        STAGE_B(0, 0);
        cp_async_commit();
        float4 va[4];
        LOAD_A(0, va);
        STORE_A(0, va);
        cp_async_wait0();
    }

    // ---- main loop
    for (int t = 0; t < KT; t++) {
        __syncthreads();
        const int cb = t & 1;
        const int nb = (t + 1) & 1;
        const bool have_next = (t + 1 < KT);

        float4 va[4];
        if (have_next) {
            STAGE_B(t + 1, nb);
            cp_async_commit();
            LOAD_A(t + 1, va);     // LDG latency covered by kk=0 compute
        }

        COMPUTE_KK(cb, 0);

        if (have_next)
            STORE_A(nb, va);       // safe: nb's last readers synced at loop top;
                                   // va dead from here -> lower reg pressure

        COMPUTE_KK(cb, 1);

        if (have_next)
            cp_async_wait0();
    }

    // ---- epilogue: float2 stores
#pragma unroll
    for (int mi = 0; mi < 2; mi++) {
        int r0 = block_row + wm * 32 + mi * 16 + g;
#pragma unroll
        for (int ni = 0; ni < 8; ni++) {
            int col = wn * 64 + ni * 8 + tig * 2;
            if (r0 < M)
                *reinterpret_cast<float2*>(C + (long long)r0 * ODIM + col) =
                    make_float2(acc[mi][ni][0], acc[mi][ni][1]);
            if (r0 + 8 < M)
                *reinterpret_cast<float2*>(C + (long long)(r0 + 8) * ODIM + col) =
                    make_float2(acc[mi][ni][2], acc[mi][ni][3]);
        }
    }
}

// ---------------------------------------------------------------------------
// kernel_launch
// inputs: 0=features[N,128] f32, 1=w1[256,128] f32, 2=w2[256,128] f32,
//         3=neighbor_idx[N,16] i32, 4=nodes[B] i32 ; out = [B,128] f32
// ---------------------------------------------------------------------------
extern "C" void kernel_launch(void* const* d_in, const int* in_sizes, int n_in,
                              void* d_out, int out_size)
{
    const float* features = (const float*)d_in[0];
    const float* w1       = (const float*)d_in[1];
    const float* w2       = (const float*)d_in[2];
    const int*   nbr      = (const int*)  d_in[3];
    const int*   nodes    = (const int*)  d_in[4];
    float*       out      = (float*)d_out;

    const int N  = in_sizes[0] / FDIM;   // 100000
    const int Bn = in_sizes[4];          // 8192

    float *agg1, *h1, *agg2;
    uint32_t *w1t_hi, *w1t_lo, *w2t_hi, *w2t_lo;
    cudaGetSymbolAddress((void**)&agg1,   g_agg1);
    cudaGetSymbolAddress((void**)&h1,     g_h1);
    cudaGetSymbolAddress((void**)&agg2,   g_agg2);
    cudaGetSymbolAddress((void**)&w1t_hi, g_w1t_hi);
    cudaGetSymbolAddress((void**)&w1t_lo, g_w1t_lo);
    cudaGetSymbolAddress((void**)&w2t_hi, g_w2t_hi);
    cudaGetSymbolAddress((void**)&w2t_lo, g_w2t_lo);

    const int smem_bytes = 8 * BUFW * 4;   // 81920 B
    static bool attr_set = false;
    if (!attr_set) {
        cudaFuncSetAttribute(gemm_tc_kernel,
                             cudaFuncAttributeMaxDynamicSharedMemorySize, smem_bytes);
        attr_set = true;
    }

    // 0) pre-split/transpose weights
    prep_w_kernel<<<64, 256>>>(w1, w1t_hi, w1t_lo);
    prep_w_kernel<<<64, 256>>>(w2, w2t_hi, w2t_lo);

    // 1) agg1 = mean neighbor features (f32 gather, LTS-cap bound)
    agg_kernel<<<(N + 7) / 8, 256>>>((const float4*)features, nbr, nullptr,
                                     (float4*)agg1, N);
    // 2) h1 = [features | agg1] @ w1   (tensor cores, pipelined)
    gemm_tc_kernel<<<(N + BM - 1) / BM, 256, smem_bytes>>>(
        features, agg1, nullptr, w1t_hi, w1t_lo, h1, N);
    // 3) agg2 = mean neighbor h1 over the batch nodes (f32 gather)
    agg_kernel<<<(Bn + 7) / 8, 256>>>((const float4*)h1, nbr, nodes,
                                      (float4*)agg2, Bn);
    // 4) out = [h1[nodes] | agg2] @ w2   (tensor cores, pipelined)
    gemm_tc_kernel<<<(Bn + BM - 1) / BM, 256, smem_bytes>>>(
        h1, agg2, nodes, w2t_hi, w2t_lo, out, Bn);
}